// round 15
// baseline (speedup 1.0000x reference)
#include <cuda_runtime.h>
#include <cuda_fp16.h>
#include <math.h>
#include <stdint.h>

#define DM 1024
#define NH 16
#define DK 64
#define B_ 2
#define S_ 2048
#define MTOT (B_*S_)   // 4096

// ---------------- scratch (device globals: allocation-free) ----------------
__device__ float2 g_cs[S_ * (DK/2)];
__device__ __half g_x[MTOT*DM];          // X fp16 (reused for attn out A)
__device__ __half g_w[4][DM*DM];
__device__ __half g_q[MTOT*DM];          // Q (pre-scaled by 0.125*log2e)
__device__ __half g_k[MTOT*DM];
__device__ __half g_v[MTOT*DM];

// ---------------- family-portable PTX helpers ----------------
__device__ __forceinline__ uint32_t smem_u32(const void* p) {
    uint32_t a;
    asm("{ .reg .u64 t; cvta.to.shared.u64 t, %1; cvt.u32.u64 %0, t; }"
        : "=r"(a) : "l"(p));
    return a;
}
#define CP16(saddr, gptr) \
    asm volatile("cp.async.cg.shared.global [%0], [%1], 16;" :: "r"(saddr), "l"(gptr))
#define CPCOMMIT() asm volatile("cp.async.commit_group;" ::: "memory")
#define CPWAIT0()  asm volatile("cp.async.wait_group 0;" ::: "memory")
#define CPWAIT1()  asm volatile("cp.async.wait_group 1;" ::: "memory")
#define LDSM4(r, addr) \
    asm volatile("ldmatrix.sync.aligned.m8n8.x4.shared.b16 {%0,%1,%2,%3}, [%4];" \
        : "=r"((r)[0]), "=r"((r)[1]), "=r"((r)[2]), "=r"((r)[3]) : "r"(addr))
#define LDSM4T(r, addr) \
    asm volatile("ldmatrix.sync.aligned.m8n8.x4.trans.shared.b16 {%0,%1,%2,%3}, [%4];" \
        : "=r"((r)[0]), "=r"((r)[1]), "=r"((r)[2]), "=r"((r)[3]) : "r"(addr))
#define MMA_F16(d, a, b) \
    asm volatile("mma.sync.aligned.m16n8k16.row.col.f32.f16.f16.f32 " \
        "{%0,%1,%2,%3},{%4,%5,%6,%7},{%8,%9},{%0,%1,%2,%3};" \
        : "+f"((d)[0]), "+f"((d)[1]), "+f"((d)[2]), "+f"((d)[3]) \
        : "r"((a)[0]), "r"((a)[1]), "r"((a)[2]), "r"((a)[3]), \
          "r"((b)[0]), "r"((b)[1]))

__device__ __forceinline__ float ex2f(float x) {
    float y; asm("ex2.approx.ftz.f32 %0, %1;" : "=f"(y) : "f"(x)); return y;
}
__device__ __forceinline__ uint32_t pk2h(float v0, float v1) {
    __half2 h = __floats2half2_rn(v0, v1);
    return *reinterpret_cast<uint32_t*>(&h);
}

#define SC2A (0.125f * 1.4426950408889634f)

// ---------------------------------------------------------------------------
__global__ void build_cs_kernel(const int* __restrict__ pos, float2* __restrict__ cs)
{
    int idx = blockIdx.x * blockDim.x + threadIdx.x;
    if (idx >= S_ * (DK/2)) return;
    int s = idx >> 5, p = idx & 31;
    float posf = (float)pos[s];
    double e   = (double)(2 * p) / (double)DK;
    float inv  = (float)exp(-e * log(10000.0));
    float ang  = posf * inv;
    cs[idx] = make_float2((float)cos((double)ang), (float)sin((double)ang));
}

__global__ void conv_x_kernel(const float* __restrict__ src, __half* __restrict__ dst, int n)
{
    int i = (blockIdx.x * blockDim.x + threadIdx.x) * 8;
    if (i >= n) return;
    float4 a = *(const float4*)(src + i);
    float4 b = *(const float4*)(src + i + 4);
    uint4 o;
    o.x = pk2h(a.x, a.y); o.y = pk2h(a.z, a.w);
    o.z = pk2h(b.x, b.y); o.w = pk2h(b.z, b.w);
    *(uint4*)(dst + i) = o;
}

__global__ void conv_w_kernel(const float* __restrict__ Wq, const float* __restrict__ Wk,
                              const float* __restrict__ Wv, const float* __restrict__ Wo,
                              __half* __restrict__ w)
{
    int gid = blockIdx.x * blockDim.x + threadIdx.x;
    int wsel = gid >> 17;
    size_t i = (size_t)(gid & 131071) * 8;
    const float* src = (wsel == 0) ? Wq : (wsel == 1) ? Wk : (wsel == 2) ? Wv : Wo;
    size_t base = (size_t)wsel * DM * DM + i;
    float4 a = *(const float4*)(src + i);
    float4 b = *(const float4*)(src + i + 4);
    uint4 o;
    o.x = pk2h(a.x, a.y); o.y = pk2h(a.z, a.w);
    o.z = pk2h(b.x, b.y); o.w = pk2h(b.z, b.w);
    *(uint4*)(w + base) = o;
}

// ---------------------------------------------------------------------------
// fp16 GEMM: Y = X @ W^T (single product). CTA tile 128x128, BK=32, 4 warps
// (warp tile 64x64, 2m x 2n). 8 LDSM4 : 32 MMA per k16. 2-stage cp.async.
// ---------------------------------------------------------------------------
#define BKK 32
#define NKB (DM / BKK)
#define SROW 40
#define T_TILE (128 * SROW * 2)                 // 10240 (128 rows x 32 cols fp16)
#define STAGE_BYTES (2 * T_TILE)                // 20480: A + B
#define GSMEM (2 * STAGE_BYTES)                 // 40960
#define OFF_A  0
#define OFF_B  T_TILE

#define GEMM_PROLOG()                                                         \
    extern __shared__ char sm[];                                              \
    const uint32_t sb = smem_u32(sm);                                         \
    const int tid  = threadIdx.x;                                             \
    const int lane = tid & 31;                                                \
    const int wid  = tid >> 5;                                                \
    const int wm   = (wid & 1) * 64;                                          \
    const int wn   = (wid >> 1) * 64;                                         \
    const int m0   = blockIdx.y * 128;                                        \
    const int n0   = blockIdx.x * 128;

#define LOAD_STAGE(sidx, kb) do {                                             \
    uint32_t sdst = sb + (sidx) * STAGE_BYTES;                                \
    int kofs = (kb) * BKK;                                                    \
    _Pragma("unroll")                                                         \
    for (int i = 0; i < 4; i++) {                                             \
        int id = tid + i * 128;                                               \
        int r = id >> 2, c = (id & 3) * 8;                                    \
        CP16(sdst + OFF_A + (r * SROW + c) * 2,                               \
             Ag_ + (size_t)(m0 + r) * DM + kofs + c);                         \
        CP16(sdst + OFF_B + (r * SROW + c) * 2,                               \
             Bg_ + (size_t)(n0 + r) * DM + kofs + c);                         \
    }                                                                         \
} while (0)

#define GEMM_MAIN()                                                           \
    float acc[4][8][4];                                                       \
    _Pragma("unroll")                                                         \
    for (int i = 0; i < 4; i++)                                               \
        _Pragma("unroll")                                                     \
        for (int j = 0; j < 8; j++)                                           \
            _Pragma("unroll")                                                 \
            for (int q = 0; q < 4; q++) acc[i][j][q] = 0.f;                   \
    LOAD_STAGE(0, 0);                                                         \
    CPCOMMIT();                                                               \
    for (int kb = 0; kb < NKB; kb++) {                                        \
        if (kb + 1 < NKB) { LOAD_STAGE((kb + 1) & 1, kb + 1); CPCOMMIT(); CPWAIT1(); } \
        else              { CPWAIT0(); }                                     \
        __syncthreads();                                                      \
        const uint32_t sst = sb + (kb & 1) * STAGE_BYTES;                     \
        _Pragma("unroll")                                                     \
        for (int kk = 0; kk < 2; kk++) {                                      \
            uint32_t af[4][4], bf[4][4];                                      \
            const int ar = wm + (lane & 15);                                  \
            const int ac = kk * 16 + (lane >> 4) * 8;                         \
            _Pragma("unroll")                                                 \
            for (int i = 0; i < 4; i++)                                       \
                LDSM4(af[i], sst + OFF_A + (((ar + i * 16) * SROW + ac) << 1)); \
            const int br = wn + ((lane >> 4) << 3) + (lane & 7);              \
            const int bc = kk * 16 + ((lane >> 3) & 1) * 8;                   \
            _Pragma("unroll")                                                 \
            for (int nb = 0; nb < 4; nb++)                                    \
                LDSM4(bf[nb], sst + OFF_B + (((br + nb * 16) * SROW + bc) << 1)); \
            _Pragma("unroll")                                                 \
            for (int nb = 0; nb < 4; nb++)                                    \
                _Pragma("unroll")                                             \
                for (int i = 0; i < 4; i++) {                                 \
                    MMA_F16(acc[i][2*nb],   af[i], &bf[nb][0]);               \
                    MMA_F16(acc[i][2*nb+1], af[i], &bf[nb][2]);               \
                }                                                             \
        }                                                                     \
        __syncthreads();                                                      \
    }

// ---- QKV projections: blockIdx.z = 0(Q: rope+scale) 1(K: rope) 2(V)
__global__ __launch_bounds__(128, 2)
void gemm_qkv(const __half* __restrict__ X, const __half* __restrict__ W,
              __half* __restrict__ q, __half* __restrict__ k, __half* __restrict__ v,
              const float2* __restrict__ cs)
{
    GEMM_PROLOG();
    const int z = blockIdx.z;
    const __half* Ag_ = X;
    const __half* Bg_ = W + (size_t)z * DM * DM;
    GEMM_MAIN();

    __half* Y = (z == 0) ? q : (z == 1) ? k : v;
#pragma unroll
    for (int i = 0; i < 4; i++)
#pragma unroll
        for (int j = 0; j < 8; j++) {
            const int col = n0 + wn + j * 8 + (lane & 3) * 2;
#pragma unroll
            for (int h = 0; h < 2; h++) {
                const int row = m0 + wm + i * 16 + (lane >> 2) + h * 8;
                float v0 = acc[i][j][h * 2], v1 = acc[i][j][h * 2 + 1];
                if (z < 2) {   // RoPE for Q,K
                    int s = row & (S_ - 1);
                    float2 cp = cs[s * 32 + ((col & (DK - 1)) >> 1)];
                    float o0 = v0 * cp.x - v1 * cp.y;
                    float o1 = v0 * cp.y + v1 * cp.x;
                    v0 = o0; v1 = o1;
                }
                if (z == 0) { v0 *= SC2A; v1 *= SC2A; }
                *(uint32_t*)(Y + (size_t)row * DM + col) = pk2h(v0, v1);
            }
        }
}

// ---- O projection: A fp16 @ Wo fp16 -> fp32 out
__global__ __launch_bounds__(128, 2)
void gemm_o(const __half* __restrict__ A, const __half* __restrict__ W,
            float* __restrict__ Y)
{
    GEMM_PROLOG();
    const __half* Ag_ = A;
    const __half* Bg_ = W;
    GEMM_MAIN();

#pragma unroll
    for (int i = 0; i < 4; i++)
#pragma unroll
        for (int j = 0; j < 8; j++) {
            const int col = n0 + wn + j * 8 + (lane & 3) * 2;
#pragma unroll
            for (int h = 0; h < 2; h++) {
                const int row = m0 + wm + i * 16 + (lane >> 2) + h * 8;
                *(float2*)(Y + (size_t)row * DM + col) =
                    make_float2(acc[i][j][h * 2], acc[i][j][h * 2 + 1]);
            }
        }
}

// ---------------------------------------------------------------------------
// Pure-fp16 causal flash attention (unchanged from round 14).
// ---------------------------------------------------------------------------
#define SP 72
#define QBB (128 * SP * 2)
#define KVB (64 * SP * 2)
#define STG (2 * KVB)
#define ATT_SMEM (QBB + 2 * STG)       // 55296

__global__ __launch_bounds__(256)
void attn_mma(const __half* __restrict__ Q, const __half* __restrict__ K,
              const __half* __restrict__ V, __half* __restrict__ Aout)
{
    extern __shared__ char sm[];
    const uint32_t sb = smem_u32(sm);
    const uint32_t sQ = sb;
    const uint32_t sStage = sb + QBB;

    const int tid = threadIdx.x, lane = tid & 31, wid = tid >> 5;
    const int qb = 15 - blockIdx.x;
    const int bh = blockIdx.y;
    const int b = bh >> 4, h = bh & 15;
    const int wm = wid * 16;
    const size_t rowbase = (size_t)b * S_;
    const int hoff = h * DK;

#pragma unroll
    for (int i = 0; i < 4; i++) {
        int id = tid + i * 256;
        int r = id >> 3, c = (id & 7) * 8;
        CP16(sQ + (r * SP + c) * 2,
             Q + (rowbase + qb * 128 + r) * DM + hoff + c);
    }

#define LOAD_KV(sidx, kb_) do {                                               \
    uint32_t dst = sStage + (sidx) * STG;                                     \
    size_t krow0 = rowbase + (size_t)(kb_) * 64;                              \
    _Pragma("unroll")                                                         \
    for (int i = 0; i < 2; i++) {                                             \
        int id = tid + i * 256;                                               \
        int r = id >> 3, c = (id & 7) * 8;                                    \
        size_t g = (krow0 + r) * DM + hoff + c;                               \
        uint32_t so = (r * SP + c) * 2;                                       \
        CP16(dst + 0 * KVB + so, K + g);                                      \
        CP16(dst + 1 * KVB + so, V + g);                                      \
    }                                                                         \
} while (0)

    LOAD_KV(0, 0);
    CPCOMMIT();

    float m2[2] = {-1e30f, -1e30f}, l[2] = {0.f, 0.f};
    float oacc[8][4];
#pragma unroll
    for (int j = 0; j < 8; j++)
#pragma unroll
        for (int q = 0; q < 4; q++) oacc[j][q] = 0.f;

    uint32_t qf[4][4];

    const uint32_t q_off  = ((uint32_t)(wm + (lane & 15)) * SP + (lane >> 4) * 8) * 2;
    const uint32_t k_loff = ((uint32_t)(((lane >> 4) << 3) + (lane & 7)) * SP
                             + ((lane >> 3) & 1) * 8) * 2;
    const uint32_t v_loff = ((uint32_t)(lane & 15) * SP + (lane >> 4) * 8) * 2;

    const int nkb = 2 * qb + 2;

    for (int kb = 0; kb < nkb; kb++) {
        if (kb + 1 < nkb) { LOAD_KV((kb + 1) & 1, kb + 1); CPCOMMIT(); CPWAIT1(); }
        else              { CPWAIT0(); }
        __syncthreads();

        if (kb == 0) {
#pragma unroll
            for (int kc = 0; kc < 4; kc++)
                LDSM4(qf[kc], sQ + q_off + kc * 32);
        }

        const uint32_t sK = sStage + (kb & 1) * STG;
        const uint32_t sV = sK + KVB;

        float sacc[8][4];
#pragma unroll
        for (int j = 0; j < 8; j++)
#pragma unroll
            for (int q = 0; q < 4; q++) sacc[j][q] = 0.f;

#pragma unroll
        for (int kc = 0; kc < 4; kc++) {
            uint32_t kf[4][4];
#pragma unroll
            for (int nb = 0; nb < 4; nb++)
                LDSM4(kf[nb], sK + (uint32_t)(nb * 16) * SP * 2 + k_loff + kc * 32);
#pragma unroll
            for (int nb = 0; nb < 4; nb++) {
                MMA_F16(sacc[2*nb],   qf[kc], &kf[nb][0]);
                MMA_F16(sacc[2*nb+1], qf[kc], &kf[nb][2]);
            }
        }

        const int grow0 = qb * 128 + wm + (lane >> 2);
        const bool diag = (kb >= 2 * qb);
        float rmx0 = -1e30f, rmx1 = -1e30f;
        if (diag) {
#pragma unroll
            for (int j = 0; j < 8; j++) {
                int cbase = kb * 64 + j * 8 + 2 * (lane & 3);
#pragma unroll
                for (int e = 0; e < 2; e++) {
                    if (cbase + e > grow0)     sacc[j][e]     = -1e30f;
                    if (cbase + e > grow0 + 8) sacc[j][2 + e] = -1e30f;
                }
            }
        }
#pragma unroll
        for (int j = 0; j < 8; j++) {
            rmx0 = fmaxf(rmx0, fmaxf(sacc[j][0], sacc[j][1]));
            rmx1 = fmaxf(rmx1, fmaxf(sacc[j][2], sacc[j][3]));
        }
        rmx0 = fmaxf(rmx0, __shfl_xor_sync(0xffffffffu, rmx0, 1));
        rmx0 = fmaxf(rmx0, __shfl_xor_sync(0xffffffffu, rmx0, 2));
        rmx1 = fmaxf(rmx1, __shfl_xor_sync(0xffffffffu, rmx1, 1));
        rmx1 = fmaxf(rmx1, __shfl_xor_sync(0xffffffffu, rmx1, 2));
        float mn0 = fmaxf(m2[0], rmx0), mn1 = fmaxf(m2[1], rmx1);

        float rs0 = 0.f, rs1 = 0.f;
#pragma unroll
        for (int j = 0; j < 8; j++) {
#pragma unroll
            for (int e = 0; e < 2; e++) {
                float p0 = ex2f(sacc[j][e] - mn0);
                float p1 = ex2f(sacc[j][2 + e] - mn1);
                sacc[j][e] = p0; sacc[j][2 + e] = p1;
                rs0 += p0; rs1 += p1;
            }
        }
        rs0 += __shfl_xor_sync(0xffffffffu, rs0, 1);
        rs0 += __shfl_xor_sync(0xffffffffu, rs0, 2);
        rs1 += __shfl_xor_sync(0xffffffffu, rs1, 1);
        rs1 += __shfl_xor_sync(0xffffffffu, rs1, 2);

        float al0 = ex2f(m2[0] - mn0), al1 = ex2f(m2[1] - mn1);
        l[0] = l[0] * al0 + rs0;
        l[1] = l[1] * al1 + rs1;
        m2[0] = mn0; m2[1] = mn1;
#pragma unroll
        for (int j = 0; j < 8; j++) {
            oacc[j][0] *= al0; oacc[j][1] *= al0;
            oacc[j][2] *= al1; oacc[j][3] *= al1;
        }

#pragma unroll
        for (int g = 0; g < 4; g++) {
            uint32_t pa[4];
            pa[0] = pk2h(sacc[2*g][0],   sacc[2*g][1]);
            pa[1] = pk2h(sacc[2*g][2],   sacc[2*g][3]);
            pa[2] = pk2h(sacc[2*g+1][0], sacc[2*g+1][1]);
            pa[3] = pk2h(sacc[2*g+1][2], sacc[2*g+1][3]);
            uint32_t vf[4][4];
#pragma unroll
            for (int nb = 0; nb < 4; nb++)
                LDSM4T(vf[nb], sV + (uint32_t)(g * 16) * SP * 2 + v_loff + nb * 32);
#pragma unroll
            for (int nb = 0; nb < 4; nb++) {
                MMA_F16(oacc[2*nb],   pa, &vf[nb][0]);
                MMA_F16(oacc[2*nb+1], pa, &vf[nb][2]);
            }
        }
        __syncthreads();
    }
#undef LOAD_KV

    float inv0 = 1.f / l[0], inv1 = 1.f / l[1];
    const size_t row0 = rowbase + (size_t)qb * 128 + wm + (lane >> 2);
#pragma unroll
    for (int j = 0; j < 8; j++) {
        const int col = hoff + j * 8 + 2 * (lane & 3);
        *(uint32_t*)(Aout + row0 * DM + col) =
            pk2h(oacc[j][0] * inv0, oacc[j][1] * inv0);
        *(uint32_t*)(Aout + (row0 + 8) * DM + col) =
            pk2h(oacc[j][2] * inv1, oacc[j][3] * inv1);
    }
}

// ---------------------------------------------------------------------------
extern "C" void kernel_launch(void* const* d_in, const int* in_sizes, int n_in,
                              void* d_out, int out_size)
{
    const float *x, *Wq, *Wk, *Wv, *Wo;
    const int* pos;
    if (in_sizes[0] == MTOT * DM) {            // setup_inputs dict order
        x   = (const float*)d_in[0];
        pos = (const int*)  d_in[1];
        Wq  = (const float*)d_in[2];
        Wk  = (const float*)d_in[3];
        Wv  = (const float*)d_in[4];
        Wo  = (const float*)d_in[5];
    } else {                                   // name-sorted order
        Wk  = (const float*)d_in[0];
        Wo  = (const float*)d_in[1];
        Wq  = (const float*)d_in[2];
        Wv  = (const float*)d_in[3];
        pos = (const int*)  d_in[4];
        x   = (const float*)d_in[5];
    }
    float* out = (float*)d_out;

    float2* cs;
    __half *xh, *w, *q, *k, *v;
    cudaGetSymbolAddress((void**)&cs, g_cs);
    cudaGetSymbolAddress((void**)&xh, g_x);
    cudaGetSymbolAddress((void**)&w,  g_w);
    cudaGetSymbolAddress((void**)&q,  g_q);
    cudaGetSymbolAddress((void**)&k,  g_k);
    cudaGetSymbolAddress((void**)&v,  g_v);

    const int NX = MTOT * DM, NW = DM * DM;

    build_cs_kernel<<<(S_ * (DK/2) + 255) / 256, 256>>>(pos, cs);          // 0
    conv_x_kernel<<<NX / 8 / 256, 256>>>(x, xh, NX);                       // 1
    conv_w_kernel<<<4 * NW / 8 / 256, 256>>>(Wq, Wk, Wv, Wo, w);           // 2

    cudaFuncSetAttribute(gemm_qkv, cudaFuncAttributeMaxDynamicSharedMemorySize, GSMEM);
    cudaFuncSetAttribute(gemm_o,   cudaFuncAttributeMaxDynamicSharedMemorySize, GSMEM);
    cudaFuncSetAttribute(attn_mma, cudaFuncAttributeMaxDynamicSharedMemorySize, ATT_SMEM);

    dim3 gq(DM / 128, MTOT / 128, 3);   // (8, 32, 3)
    gemm_qkv<<<gq, 128, GSMEM>>>(xh, w, q, k, v, cs);                      // 3

    attn_mma<<<dim3(16, B_ * NH), 256, ATT_SMEM>>>(q, k, v, xh);           // 4

    dim3 gg(DM / 128, MTOT / 128);      // (8, 32)
    gemm_o<<<gg, 128, GSMEM>>>(xh, w + 3 * (size_t)NW, out);               // 5 <- profiled
}

// round 16
// speedup vs baseline: 1.5517x; 1.5517x over previous
#include <cuda_runtime.h>
#include <cuda_fp16.h>
#include <math.h>
#include <stdint.h>

#define DM 1024
#define NH 16
#define DK 64
#define B_ 2
#define S_ 2048
#define MTOT (B_*S_)   // 4096

// ---------------- scratch (device globals: allocation-free) ----------------
__device__ float2 g_cs[S_ * (DK/2)];
__device__ __half g_x[MTOT*DM];          // X fp16 (reused for attn out A)
__device__ __half g_w[4][DM*DM];
__device__ __half g_q[MTOT*DM];          // Q (pre-scaled by 0.125*log2e)
__device__ __half g_k[MTOT*DM];
__device__ __half g_v[MTOT*DM];

// ---------------- family-portable PTX helpers ----------------
__device__ __forceinline__ uint32_t smem_u32(const void* p) {
    uint32_t a;
    asm("{ .reg .u64 t; cvta.to.shared.u64 t, %1; cvt.u32.u64 %0, t; }"
        : "=r"(a) : "l"(p));
    return a;
}
#define CP16(saddr, gptr) \
    asm volatile("cp.async.cg.shared.global [%0], [%1], 16;" :: "r"(saddr), "l"(gptr))
#define CPCOMMIT() asm volatile("cp.async.commit_group;" ::: "memory")
#define CPWAIT0()  asm volatile("cp.async.wait_group 0;" ::: "memory")
#define CPWAIT1()  asm volatile("cp.async.wait_group 1;" ::: "memory")
#define LDSM4(r, addr) \
    asm volatile("ldmatrix.sync.aligned.m8n8.x4.shared.b16 {%0,%1,%2,%3}, [%4];" \
        : "=r"((r)[0]), "=r"((r)[1]), "=r"((r)[2]), "=r"((r)[3]) : "r"(addr))
#define LDSM4T(r, addr) \
    asm volatile("ldmatrix.sync.aligned.m8n8.x4.trans.shared.b16 {%0,%1,%2,%3}, [%4];" \
        : "=r"((r)[0]), "=r"((r)[1]), "=r"((r)[2]), "=r"((r)[3]) : "r"(addr))
#define MMA_F16(d, a, b) \
    asm volatile("mma.sync.aligned.m16n8k16.row.col.f32.f16.f16.f32 " \
        "{%0,%1,%2,%3},{%4,%5,%6,%7},{%8,%9},{%0,%1,%2,%3};" \
        : "+f"((d)[0]), "+f"((d)[1]), "+f"((d)[2]), "+f"((d)[3]) \
        : "r"((a)[0]), "r"((a)[1]), "r"((a)[2]), "r"((a)[3]), \
          "r"((b)[0]), "r"((b)[1]))

__device__ __forceinline__ float ex2f(float x) {
    float y; asm("ex2.approx.ftz.f32 %0, %1;" : "=f"(y) : "f"(x)); return y;
}
__device__ __forceinline__ uint32_t pk2h(float v0, float v1) {
    __half2 h = __floats2half2_rn(v0, v1);
    return *reinterpret_cast<uint32_t*>(&h);
}

#define SC2A (0.125f * 1.4426950408889634f)

// ---------------------------------------------------------------------------
__global__ void build_cs_kernel(const int* __restrict__ pos, float2* __restrict__ cs)
{
    int idx = blockIdx.x * blockDim.x + threadIdx.x;
    if (idx >= S_ * (DK/2)) return;
    int s = idx >> 5, p = idx & 31;
    float posf = (float)pos[s];
    double e   = (double)(2 * p) / (double)DK;
    float inv  = (float)exp(-e * log(10000.0));
    float ang  = posf * inv;
    cs[idx] = make_float2((float)cos((double)ang), (float)sin((double)ang));
}

__global__ void conv_x_kernel(const float* __restrict__ src, __half* __restrict__ dst, int n)
{
    int i = (blockIdx.x * blockDim.x + threadIdx.x) * 8;
    if (i >= n) return;
    float4 a = *(const float4*)(src + i);
    float4 b = *(const float4*)(src + i + 4);
    uint4 o;
    o.x = pk2h(a.x, a.y); o.y = pk2h(a.z, a.w);
    o.z = pk2h(b.x, b.y); o.w = pk2h(b.z, b.w);
    *(uint4*)(dst + i) = o;
}

__global__ void conv_w_kernel(const float* __restrict__ Wq, const float* __restrict__ Wk,
                              const float* __restrict__ Wv, const float* __restrict__ Wo,
                              __half* __restrict__ w)
{
    int gid = blockIdx.x * blockDim.x + threadIdx.x;
    int wsel = gid >> 17;
    size_t i = (size_t)(gid & 131071) * 8;
    const float* src = (wsel == 0) ? Wq : (wsel == 1) ? Wk : (wsel == 2) ? Wv : Wo;
    size_t base = (size_t)wsel * DM * DM + i;
    float4 a = *(const float4*)(src + i);
    float4 b = *(const float4*)(src + i + 4);
    uint4 o;
    o.x = pk2h(a.x, a.y); o.y = pk2h(a.z, a.w);
    o.z = pk2h(b.x, b.y); o.w = pk2h(b.z, b.w);
    *(uint4*)(w + base) = o;
}

// ---------------------------------------------------------------------------
// fp16 GEMM: Y = X @ W^T. CTA tile 128x64, BK=64 (deep-K), 4 warps (64x32).
// Barrier/pipeline overhead amortized over 2x MMAs vs BK=32. 2-stage cp.async.
// ---------------------------------------------------------------------------
#define BKK 64
#define NKB (DM / BKK)                          // 16
#define SROW 72
#define A_TILE (128 * SROW * 2)                 // 18432
#define B_TILE (64 * SROW * 2)                  // 9216
#define STAGE_BYTES (A_TILE + B_TILE)           // 27648
#define GSMEM (2 * STAGE_BYTES)                 // 55296
#define OFF_A  0
#define OFF_B  A_TILE

#define GEMM_PROLOG()                                                         \
    extern __shared__ char sm[];                                              \
    const uint32_t sb = smem_u32(sm);                                         \
    const int tid  = threadIdx.x;                                             \
    const int lane = tid & 31;                                                \
    const int wid  = tid >> 5;                                                \
    const int wm   = (wid & 1) * 64;                                          \
    const int wn   = (wid >> 1) * 32;                                         \
    const int m0   = blockIdx.y * 128;                                        \
    const int n0   = blockIdx.x * 64;

#define LOAD_STAGE(sidx, kb) do {                                             \
    uint32_t sdst = sb + (sidx) * STAGE_BYTES;                                \
    int kofs = (kb) * BKK;                                                    \
    _Pragma("unroll")                                                         \
    for (int i = 0; i < 8; i++) {    /* A: 128 rows x 64 cols */              \
        int id = tid + i * 128;                                               \
        int r = id >> 3, c = (id & 7) * 8;                                    \
        CP16(sdst + OFF_A + (r * SROW + c) * 2,                               \
             Ag_ + (size_t)(m0 + r) * DM + kofs + c);                         \
    }                                                                         \
    _Pragma("unroll")                                                         \
    for (int i = 0; i < 4; i++) {    /* B: 64 rows x 64 cols */               \
        int id = tid + i * 128;                                               \
        int r = id >> 3, c = (id & 7) * 8;                                    \
        CP16(sdst + OFF_B + (r * SROW + c) * 2,                               \
             Bg_ + (size_t)(n0 + r) * DM + kofs + c);                         \
    }                                                                         \
} while (0)

#define GEMM_MAIN()                                                           \
    float acc[4][4][4];                                                       \
    _Pragma("unroll")                                                         \
    for (int i = 0; i < 4; i++)                                               \
        _Pragma("unroll")                                                     \
        for (int j = 0; j < 4; j++)                                           \
            _Pragma("unroll")                                                 \
            for (int q = 0; q < 4; q++) acc[i][j][q] = 0.f;                   \
    LOAD_STAGE(0, 0);                                                         \
    CPCOMMIT();                                                               \
    for (int kb = 0; kb < NKB; kb++) {                                        \
        if (kb + 1 < NKB) { LOAD_STAGE((kb + 1) & 1, kb + 1); CPCOMMIT(); CPWAIT1(); } \
        else              { CPWAIT0(); }                                     \
        __syncthreads();                                                      \
        const uint32_t sst = sb + (kb & 1) * STAGE_BYTES;                     \
        _Pragma("unroll")                                                     \
        for (int kk = 0; kk < 4; kk++) {                                      \
            uint32_t af[4][4], bf[2][4];                                      \
            const int ar = wm + (lane & 15);                                  \
            const int ac = kk * 16 + (lane >> 4) * 8;                         \
            _Pragma("unroll")                                                 \
            for (int i = 0; i < 4; i++)                                       \
                LDSM4(af[i], sst + OFF_A + (((ar + i * 16) * SROW + ac) << 1)); \
            const int br = wn + ((lane >> 4) << 3) + (lane & 7);              \
            const int bc = kk * 16 + ((lane >> 3) & 1) * 8;                   \
            _Pragma("unroll")                                                 \
            for (int nb = 0; nb < 2; nb++)                                    \
                LDSM4(bf[nb], sst + OFF_B + (((br + nb * 16) * SROW + bc) << 1)); \
            _Pragma("unroll")                                                 \
            for (int nb = 0; nb < 2; nb++)                                    \
                _Pragma("unroll")                                             \
                for (int i = 0; i < 4; i++) {                                 \
                    MMA_F16(acc[i][2*nb],   af[i], &bf[nb][0]);               \
                    MMA_F16(acc[i][2*nb+1], af[i], &bf[nb][2]);               \
                }                                                             \
        }                                                                     \
        __syncthreads();                                                      \
    }

// ---- QKV projections: blockIdx.z = 0(Q: rope+scale) 1(K: rope) 2(V)
__global__ __launch_bounds__(128, 3)
void gemm_qkv(const __half* __restrict__ X, const __half* __restrict__ W,
              __half* __restrict__ q, __half* __restrict__ k, __half* __restrict__ v,
              const float2* __restrict__ cs)
{
    GEMM_PROLOG();
    const int z = blockIdx.z;
    const __half* Ag_ = X;
    const __half* Bg_ = W + (size_t)z * DM * DM;
    GEMM_MAIN();

    __half* Y = (z == 0) ? q : (z == 1) ? k : v;
#pragma unroll
    for (int i = 0; i < 4; i++)
#pragma unroll
        for (int j = 0; j < 4; j++) {
            const int col = n0 + wn + j * 8 + (lane & 3) * 2;
#pragma unroll
            for (int h = 0; h < 2; h++) {
                const int row = m0 + wm + i * 16 + (lane >> 2) + h * 8;
                float v0 = acc[i][j][h * 2], v1 = acc[i][j][h * 2 + 1];
                if (z < 2) {   // RoPE for Q,K
                    int s = row & (S_ - 1);
                    float2 cp = cs[s * 32 + ((col & (DK - 1)) >> 1)];
                    float o0 = v0 * cp.x - v1 * cp.y;
                    float o1 = v0 * cp.y + v1 * cp.x;
                    v0 = o0; v1 = o1;
                }
                if (z == 0) { v0 *= SC2A; v1 *= SC2A; }
                *(uint32_t*)(Y + (size_t)row * DM + col) = pk2h(v0, v1);
            }
        }
}

// ---- O projection: A fp16 @ Wo fp16 -> fp32 out
__global__ __launch_bounds__(128, 3)
void gemm_o(const __half* __restrict__ A, const __half* __restrict__ W,
            float* __restrict__ Y)
{
    GEMM_PROLOG();
    const __half* Ag_ = A;
    const __half* Bg_ = W;
    GEMM_MAIN();

#pragma unroll
    for (int i = 0; i < 4; i++)
#pragma unroll
        for (int j = 0; j < 4; j++) {
            const int col = n0 + wn + j * 8 + (lane & 3) * 2;
#pragma unroll
            for (int h = 0; h < 2; h++) {
                const int row = m0 + wm + i * 16 + (lane >> 2) + h * 8;
                *(float2*)(Y + (size_t)row * DM + col) =
                    make_float2(acc[i][j][h * 2], acc[i][j][h * 2 + 1]);
            }
        }
}

// ---------------------------------------------------------------------------
// Pure-fp16 causal flash attention (round-14 proven, unchanged).
// ---------------------------------------------------------------------------
#define SP 72
#define QBB (128 * SP * 2)
#define KVB (64 * SP * 2)
#define STG (2 * KVB)
#define ATT_SMEM (QBB + 2 * STG)       // 55296

__global__ __launch_bounds__(256)
void attn_mma(const __half* __restrict__ Q, const __half* __restrict__ K,
              const __half* __restrict__ V, __half* __restrict__ Aout)
{
    extern __shared__ char sm[];
    const uint32_t sb = smem_u32(sm);
    const uint32_t sQ = sb;
    const uint32_t sStage = sb + QBB;

    const int tid = threadIdx.x, lane = tid & 31, wid = tid >> 5;
    const int qb = 15 - blockIdx.x;
    const int bh = blockIdx.y;
    const int b = bh >> 4, h = bh & 15;
    const int wm = wid * 16;
    const size_t rowbase = (size_t)b * S_;
    const int hoff = h * DK;

#pragma unroll
    for (int i = 0; i < 4; i++) {
        int id = tid + i * 256;
        int r = id >> 3, c = (id & 7) * 8;
        CP16(sQ + (r * SP + c) * 2,
             Q + (rowbase + qb * 128 + r) * DM + hoff + c);
    }

#define LOAD_KV(sidx, kb_) do {                                               \
    uint32_t dst = sStage + (sidx) * STG;                                     \
    size_t krow0 = rowbase + (size_t)(kb_) * 64;                              \
    _Pragma("unroll")                                                         \
    for (int i = 0; i < 2; i++) {                                             \
        int id = tid + i * 256;                                               \
        int r = id >> 3, c = (id & 7) * 8;                                    \
        size_t g = (krow0 + r) * DM + hoff + c;                               \
        uint32_t so = (r * SP + c) * 2;                                       \
        CP16(dst + 0 * KVB + so, K + g);                                      \
        CP16(dst + 1 * KVB + so, V + g);                                      \
    }                                                                         \
} while (0)

    LOAD_KV(0, 0);
    CPCOMMIT();

    float m2[2] = {-1e30f, -1e30f}, l[2] = {0.f, 0.f};
    float oacc[8][4];
#pragma unroll
    for (int j = 0; j < 8; j++)
#pragma unroll
        for (int q = 0; q < 4; q++) oacc[j][q] = 0.f;

    uint32_t qf[4][4];

    const uint32_t q_off  = ((uint32_t)(wm + (lane & 15)) * SP + (lane >> 4) * 8) * 2;
    const uint32_t k_loff = ((uint32_t)(((lane >> 4) << 3) + (lane & 7)) * SP
                             + ((lane >> 3) & 1) * 8) * 2;
    const uint32_t v_loff = ((uint32_t)(lane & 15) * SP + (lane >> 4) * 8) * 2;

    const int nkb = 2 * qb + 2;

    for (int kb = 0; kb < nkb; kb++) {
        if (kb + 1 < nkb) { LOAD_KV((kb + 1) & 1, kb + 1); CPCOMMIT(); CPWAIT1(); }
        else              { CPWAIT0(); }
        __syncthreads();

        if (kb == 0) {
#pragma unroll
            for (int kc = 0; kc < 4; kc++)
                LDSM4(qf[kc], sQ + q_off + kc * 32);
        }

        const uint32_t sK = sStage + (kb & 1) * STG;
        const uint32_t sV = sK + KVB;

        float sacc[8][4];
#pragma unroll
        for (int j = 0; j < 8; j++)
#pragma unroll
            for (int q = 0; q < 4; q++) sacc[j][q] = 0.f;

#pragma unroll
        for (int kc = 0; kc < 4; kc++) {
            uint32_t kf[4][4];
#pragma unroll
            for (int nb = 0; nb < 4; nb++)
                LDSM4(kf[nb], sK + (uint32_t)(nb * 16) * SP * 2 + k_loff + kc * 32);
#pragma unroll
            for (int nb = 0; nb < 4; nb++) {
                MMA_F16(sacc[2*nb],   qf[kc], &kf[nb][0]);
                MMA_F16(sacc[2*nb+1], qf[kc], &kf[nb][2]);
            }
        }

        const int grow0 = qb * 128 + wm + (lane >> 2);
        const bool diag = (kb >= 2 * qb);
        float rmx0 = -1e30f, rmx1 = -1e30f;
        if (diag) {
#pragma unroll
            for (int j = 0; j < 8; j++) {
                int cbase = kb * 64 + j * 8 + 2 * (lane & 3);
#pragma unroll
                for (int e = 0; e < 2; e++) {
                    if (cbase + e > grow0)     sacc[j][e]     = -1e30f;
                    if (cbase + e > grow0 + 8) sacc[j][2 + e] = -1e30f;
                }
            }
        }
#pragma unroll
        for (int j = 0; j < 8; j++) {
            rmx0 = fmaxf(rmx0, fmaxf(sacc[j][0], sacc[j][1]));
            rmx1 = fmaxf(rmx1, fmaxf(sacc[j][2], sacc[j][3]));
        }
        rmx0 = fmaxf(rmx0, __shfl_xor_sync(0xffffffffu, rmx0, 1));
        rmx0 = fmaxf(rmx0, __shfl_xor_sync(0xffffffffu, rmx0, 2));
        rmx1 = fmaxf(rmx1, __shfl_xor_sync(0xffffffffu, rmx1, 1));
        rmx1 = fmaxf(rmx1, __shfl_xor_sync(0xffffffffu, rmx1, 2));
        float mn0 = fmaxf(m2[0], rmx0), mn1 = fmaxf(m2[1], rmx1);

        float rs0 = 0.f, rs1 = 0.f;
#pragma unroll
        for (int j = 0; j < 8; j++) {
#pragma unroll
            for (int e = 0; e < 2; e++) {
                float p0 = ex2f(sacc[j][e] - mn0);
                float p1 = ex2f(sacc[j][2 + e] - mn1);
                sacc[j][e] = p0; sacc[j][2 + e] = p1;
                rs0 += p0; rs1 += p1;
            }
        }
        rs0 += __shfl_xor_sync(0xffffffffu, rs0, 1);
        rs0 += __shfl_xor_sync(0xffffffffu, rs0, 2);
        rs1 += __shfl_xor_sync(0xffffffffu, rs1, 1);
        rs1 += __shfl_xor_sync(0xffffffffu, rs1, 2);

        float al0 = ex2f(m2[0] - mn0), al1 = ex2f(m2[1] - mn1);
        l[0] = l[0] * al0 + rs0;
        l[1] = l[1] * al1 + rs1;
        m2[0] = mn0; m2[1] = mn1;
#pragma unroll
        for (int j = 0; j < 8; j++) {
            oacc[j][0] *= al0; oacc[j][1] *= al0;
            oacc[j][2] *= al1; oacc[j][3] *= al1;
        }

#pragma unroll
        for (int g = 0; g < 4; g++) {
            uint32_t pa[4];
            pa[0] = pk2h(sacc[2*g][0],   sacc[2*g][1]);
            pa[1] = pk2h(sacc[2*g][2],   sacc[2*g][3]);
            pa[2] = pk2h(sacc[2*g+1][0], sacc[2*g+1][1]);
            pa[3] = pk2h(sacc[2*g+1][2], sacc[2*g+1][3]);
            uint32_t vf[4][4];
#pragma unroll
            for (int nb = 0; nb < 4; nb++)
                LDSM4T(vf[nb], sV + (uint32_t)(g * 16) * SP * 2 + v_loff + nb * 32);
#pragma unroll
            for (int nb = 0; nb < 4; nb++) {
                MMA_F16(oacc[2*nb],   pa, &vf[nb][0]);
                MMA_F16(oacc[2*nb+1], pa, &vf[nb][2]);
            }
        }
        __syncthreads();
    }
#undef LOAD_KV

    float inv0 = 1.f / l[0], inv1 = 1.f / l[1];
    const size_t row0 = rowbase + (size_t)qb * 128 + wm + (lane >> 2);
#pragma unroll
    for (int j = 0; j < 8; j++) {
        const int col = hoff + j * 8 + 2 * (lane & 3);
        *(uint32_t*)(Aout + row0 * DM + col) =
            pk2h(oacc[j][0] * inv0, oacc[j][1] * inv0);
        *(uint32_t*)(Aout + (row0 + 8) * DM + col) =
            pk2h(oacc[j][2] * inv1, oacc[j][3] * inv1);
    }
}

// ---------------------------------------------------------------------------
extern "C" void kernel_launch(void* const* d_in, const int* in_sizes, int n_in,
                              void* d_out, int out_size)
{
    const float *x, *Wq, *Wk, *Wv, *Wo;
    const int* pos;
    if (in_sizes[0] == MTOT * DM) {            // setup_inputs dict order
        x   = (const float*)d_in[0];
        pos = (const int*)  d_in[1];
        Wq  = (const float*)d_in[2];
        Wk  = (const float*)d_in[3];
        Wv  = (const float*)d_in[4];
        Wo  = (const float*)d_in[5];
    } else {                                   // name-sorted order
        Wk  = (const float*)d_in[0];
        Wo  = (const float*)d_in[1];
        Wq  = (const float*)d_in[2];
        Wv  = (const float*)d_in[3];
        pos = (const int*)  d_in[4];
        x   = (const float*)d_in[5];
    }
    float* out = (float*)d_out;

    float2* cs;
    __half *xh, *w, *q, *k, *v;
    cudaGetSymbolAddress((void**)&cs, g_cs);
    cudaGetSymbolAddress((void**)&xh, g_x);
    cudaGetSymbolAddress((void**)&w,  g_w);
    cudaGetSymbolAddress((void**)&q,  g_q);
    cudaGetSymbolAddress((void**)&k,  g_k);
    cudaGetSymbolAddress((void**)&v,  g_v);

    const int NX = MTOT * DM, NW = DM * DM;

    build_cs_kernel<<<(S_ * (DK/2) + 255) / 256, 256>>>(pos, cs);          // 0
    conv_x_kernel<<<NX / 8 / 256, 256>>>(x, xh, NX);                       // 1
    conv_w_kernel<<<4 * NW / 8 / 256, 256>>>(Wq, Wk, Wv, Wo, w);           // 2

    cudaFuncSetAttribute(gemm_qkv, cudaFuncAttributeMaxDynamicSharedMemorySize, GSMEM);
    cudaFuncSetAttribute(gemm_o,   cudaFuncAttributeMaxDynamicSharedMemorySize, GSMEM);
    cudaFuncSetAttribute(attn_mma, cudaFuncAttributeMaxDynamicSharedMemorySize, ATT_SMEM);

    dim3 gq(DM / 64, MTOT / 128, 3);    // (16, 32, 3)
    gemm_qkv<<<gq, 128, GSMEM>>>(xh, w, q, k, v, cs);                      // 3

    attn_mma<<<dim3(16, B_ * NH), 256, ATT_SMEM>>>(q, k, v, xh);           // 4

    dim3 gg(DM / 64, MTOT / 128);       // (16, 32)
    gemm_o<<<gg, 128, GSMEM>>>(xh, w + 3 * (size_t)NW, out);               // 5 <- profiled
}